// round 2
// baseline (speedup 1.0000x reference)
#include <cuda_runtime.h>
#include <math.h>

// ---------------------------------------------------------------------------
// Problem constants (fixed shapes from the reference)
// ---------------------------------------------------------------------------
#define BATCH     4
#define TLEN      4096
#define MTOK      (BATCH * TLEN)      // 16384 tokens
#define DIM       1024
#define DINNER    2048
#define DSTATE    16
#define KCONV     4

// ---------------------------------------------------------------------------
// Scratch buffers (static device globals; no allocation anywhere)
// ---------------------------------------------------------------------------
__device__ float g_xz   [(size_t)MTOK * 2 * DINNER];   // (16384, 4096): x_in | gate
__device__ float g_xs1  [(size_t)(MTOK/2) * DINNER];   // downsampled s=1
__device__ float g_xs2  [(size_t)(MTOK/4) * DINNER];   // downsampled s=2
__device__ float g_y0   [(size_t)MTOK     * DINNER];   // xc -> y  (scale 0)
__device__ float g_y1   [(size_t)(MTOK/2) * DINNER];
__device__ float g_y2   [(size_t)(MTOK/4) * DINNER];
__device__ float g_B0   [(size_t)MTOK     * DSTATE];
__device__ float g_B1   [(size_t)(MTOK/2) * DSTATE];
__device__ float g_B2   [(size_t)(MTOK/4) * DSTATE];
__device__ float g_fused[(size_t)MTOK * DINNER];
__device__ float g_ctx  [(size_t)MTOK * DINNER];
__device__ float g_h    [(size_t)MTOK * (DINNER/2)];

// ---------------------------------------------------------------------------
// Math helpers
// ---------------------------------------------------------------------------
__device__ __forceinline__ float sigmoidf_(float x) { return 1.0f / (1.0f + expf(-x)); }
__device__ __forceinline__ float siluf_(float x)    { return x / (1.0f + expf(-x)); }
__device__ __forceinline__ float softplusf_(float x) {
    return x > 0.0f ? x + log1pf(expf(-x)) : log1pf(expf(x));
}

// ---------------------------------------------------------------------------
// Tiled SGEMM: C[M,N] = A[M,K] @ B[K,N]   (all row-major, dims divisible:
// M % 128 == 0, N % 128 == 0, K % 16 == 0)
// EPI: 0 = plain store, 1 = silu, 2 = cg-combine (C in/out = fused),
//      3 = +residual
// ---------------------------------------------------------------------------
#define BM 128
#define BN 128
#define BK 16

template <int EPI>
__global__ __launch_bounds__(256)
void sgemm_kernel(const float* __restrict__ A, const float* __restrict__ B,
                  float* __restrict__ C, int M, int N, int K,
                  const float* __restrict__ aux)
{
    __shared__ float As[BK][BM + 4];
    __shared__ float Bs[BK][BN];

    const int tid = threadIdx.x;
    const int bx = blockIdx.x;   // N tile
    const int by = blockIdx.y;   // M tile
    const int tx = tid & 15;     // 0..15 -> 8 cols each
    const int ty = tid >> 4;     // 0..15 -> 8 rows each

    const int aRow = tid >> 2;          // 0..63
    const int aCol = (tid & 3) << 2;    // 0,4,8,12
    const int bRow = tid >> 5;          // 0..7
    const int bCol = (tid & 31) << 2;   // 0..124

    const float* Ap = A + (size_t)(by * BM) * K;
    const float* Bp = B + (size_t)(bx * BN);

    float acc[8][8];
#pragma unroll
    for (int i = 0; i < 8; i++)
#pragma unroll
        for (int j = 0; j < 8; j++) acc[i][j] = 0.0f;

    for (int k0 = 0; k0 < K; k0 += BK) {
        float4 a0 = *(const float4*)(Ap + (size_t)aRow * K + k0 + aCol);
        float4 a1 = *(const float4*)(Ap + (size_t)(aRow + 64) * K + k0 + aCol);
        As[aCol + 0][aRow] = a0.x; As[aCol + 1][aRow] = a0.y;
        As[aCol + 2][aRow] = a0.z; As[aCol + 3][aRow] = a0.w;
        As[aCol + 0][aRow + 64] = a1.x; As[aCol + 1][aRow + 64] = a1.y;
        As[aCol + 2][aRow + 64] = a1.z; As[aCol + 3][aRow + 64] = a1.w;

        float4 b0 = *(const float4*)(Bp + (size_t)(k0 + bRow) * N + bCol);
        float4 b1 = *(const float4*)(Bp + (size_t)(k0 + bRow + 8) * N + bCol);
        *(float4*)&Bs[bRow][bCol]     = b0;
        *(float4*)&Bs[bRow + 8][bCol] = b1;

        __syncthreads();

#pragma unroll
        for (int kk = 0; kk < BK; kk++) {
            float ar[8], br[8];
            *(float4*)&ar[0] = *(const float4*)&As[kk][ty * 8];
            *(float4*)&ar[4] = *(const float4*)&As[kk][ty * 8 + 4];
            *(float4*)&br[0] = *(const float4*)&Bs[kk][tx * 8];
            *(float4*)&br[4] = *(const float4*)&Bs[kk][tx * 8 + 4];
#pragma unroll
            for (int i = 0; i < 8; i++)
#pragma unroll
                for (int j = 0; j < 8; j++) acc[i][j] += ar[i] * br[j];
        }
        __syncthreads();
    }

#pragma unroll
    for (int i = 0; i < 8; i++) {
        const int row = by * BM + ty * 8 + i;
        const size_t base = (size_t)row * N + bx * BN + tx * 8;
#pragma unroll
        for (int j = 0; j < 8; j++) {
            float v = acc[i][j];
            if (EPI == 0) {
                C[base + j] = v;
            } else if (EPI == 1) {
                C[base + j] = siluf_(v);
            } else if (EPI == 2) {
                // C (= fused) *= sigmoid(v) * silu(gate)
                const int col = bx * BN + tx * 8 + j;
                const float gate = aux[(size_t)row * (2 * DINNER) + DINNER + col];
                C[base + j] = C[base + j] * sigmoidf_(v) * siluf_(gate);
            } else {
                C[base + j] = v + aux[base + j];   // residual (N == DIM)
            }
        }
    }
}

// ---------------------------------------------------------------------------
// Downsample (mean pooling over time, factor 2 or 4) from x_in half of g_xz
// ---------------------------------------------------------------------------
__global__ void down_kernel(const float* __restrict__ xz, float* __restrict__ out,
                            int factor, int Tout)
{
    const int r = blockIdx.x;                // 0 .. B*Tout-1
    const int b = r / Tout, t = r % Tout;
    const float inv = 1.0f / (float)factor;
    const size_t srow = ((size_t)b * TLEN + (size_t)t * factor) * (2 * DINNER);
    for (int c = threadIdx.x; c < DINNER; c += 256) {
        float s = 0.0f;
        for (int k = 0; k < factor; k++)
            s += xz[srow + (size_t)k * (2 * DINNER) + c];
        out[(size_t)r * DINNER + c] = s * inv;
    }
}

// ---------------------------------------------------------------------------
// Causal depthwise conv (K=4) + SiLU.  X has row stride xstride (4096 for the
// in-place x_in view inside g_xz, 2048 for the downsampled buffers).
// ---------------------------------------------------------------------------
__global__ void conv_silu_kernel(const float* __restrict__ X, int xstride,
                                 const float* __restrict__ w,
                                 const float* __restrict__ bias,
                                 float* __restrict__ out, int Ts)
{
    const int r = blockIdx.x;                // global row = b*Ts + t
    const int b = r / Ts, t = r % Ts;
    for (int c = threadIdx.x; c < DINNER; c += 256) {
        float acc = bias[c];
#pragma unroll
        for (int k = 0; k < KCONV; k++) {
            const int tt = t - (KCONV - 1) + k;
            if (tt >= 0)
                acc += w[c * KCONV + k] * X[((size_t)(b * Ts + tt)) * xstride + c];
        }
        out[(size_t)r * DINNER + c] = siluf_(acc);
    }
}

// ---------------------------------------------------------------------------
// B_ssm = (xc @ xproj_w[:, :16])  — skinny GEMM, one block per row
// ---------------------------------------------------------------------------
__global__ void bssm_kernel(const float* __restrict__ xc,
                            const float* __restrict__ xw,   // (2048, 32)
                            float* __restrict__ Bout)
{
    const int row = blockIdx.x;
    const int tid = threadIdx.x;
    const int col = tid & 15;     // 0..15
    const int grp = tid >> 4;     // 0..15, each owns a 128-wide K slice
    const float* xr = xc + (size_t)row * DINNER;
    float acc = 0.0f;
    const int k0 = grp * 128;
#pragma unroll 8
    for (int k = k0; k < k0 + 128; k++)
        acc += xr[k] * xw[k * (2 * DSTATE) + col];
    __shared__ float sh[16][16];
    sh[grp][col] = acc;
    __syncthreads();
    if (tid < 16) {
        float s = 0.0f;
#pragma unroll
        for (int g = 0; g < 16; g++) s += sh[g][tid];
        Bout[(size_t)row * DSTATE + tid] = s;
    }
}

// ---------------------------------------------------------------------------
// dt = softplus(B_ssm @ dtw + dtb);  y = xc * sigmoid(dt) + D * x_s
// (in-place: y overwrites xc buffer)
// ---------------------------------------------------------------------------
__global__ void dty_kernel(float* __restrict__ y,              // in: xc / out: y
                           const float* __restrict__ Bssm,
                           const float* __restrict__ dtw,      // (16, 2048)
                           const float* __restrict__ dtb,
                           const float* __restrict__ Dp,
                           const float* __restrict__ xs, int xs_stride)
{
    const int row = blockIdx.x;
    __shared__ float Bv[DSTATE];
    if (threadIdx.x < DSTATE)
        Bv[threadIdx.x] = Bssm[(size_t)row * DSTATE + threadIdx.x];
    __syncthreads();
    for (int c = threadIdx.x; c < DINNER; c += 256) {
        float logit = dtb[c];
#pragma unroll
        for (int j = 0; j < DSTATE; j++)
            logit += Bv[j] * dtw[j * DINNER + c];
        const float dt = softplusf_(logit);
        const float xcv = y[(size_t)row * DINNER + c];
        y[(size_t)row * DINNER + c] =
            xcv * sigmoidf_(dt) + Dp[c] * xs[(size_t)row * xs_stride + c];
    }
}

// ---------------------------------------------------------------------------
// Linear upsample of scale-1/2 outputs + softmax-weighted mix + ctx average
// ---------------------------------------------------------------------------
__global__ void mix_kernel(const float* __restrict__ y0,
                           const float* __restrict__ y1,
                           const float* __restrict__ y2,
                           const float* __restrict__ sw,
                           float* __restrict__ fused, float* __restrict__ ctx)
{
    const int r = blockIdx.x;                 // 0..16383
    const int b = r >> 12, t = r & (TLEN - 1);

    const float s0 = sw[0], s1 = sw[1], s2 = sw[2];
    const float m  = fmaxf(s0, fmaxf(s1, s2));
    const float e0 = expf(s0 - m), e1 = expf(s1 - m), e2 = expf(s2 - m);
    const float inv = 1.0f / (e0 + e1 + e2);
    const float w0 = e0 * inv, w1 = e1 * inv, w2 = e2 * inv;

    // align_corners=False linear interpolation indices
    float c1 = fminf(fmaxf((t + 0.5f) * 0.5f - 0.5f, 0.0f), (float)(TLEN / 2 - 1));
    int lo1 = (int)floorf(c1);
    int hi1 = min(lo1 + 1, TLEN / 2 - 1);
    float f1 = c1 - (float)lo1;

    float c2 = fminf(fmaxf((t + 0.5f) * 0.25f - 0.5f, 0.0f), (float)(TLEN / 4 - 1));
    int lo2 = (int)floorf(c2);
    int hi2 = min(lo2 + 1, TLEN / 4 - 1);
    float f2 = c2 - (float)lo2;

    const float* p0  = y0 + (size_t)r * DINNER;
    const float* p1a = y1 + ((size_t)(b * (TLEN / 2) + lo1)) * DINNER;
    const float* p1b = y1 + ((size_t)(b * (TLEN / 2) + hi1)) * DINNER;
    const float* p2a = y2 + ((size_t)(b * (TLEN / 4) + lo2)) * DINNER;
    const float* p2b = y2 + ((size_t)(b * (TLEN / 4) + hi2)) * DINNER;

    for (int c = threadIdx.x; c < DINNER; c += 256) {
        const float v0 = p0[c];
        const float v1 = p1a[c] * (1.0f - f1) + p1b[c] * f1;
        const float v2 = p2a[c] * (1.0f - f2) + p2b[c] * f2;
        fused[(size_t)r * DINNER + c] = w0 * v0 + w1 * v1 + w2 * v2;
        ctx  [(size_t)r * DINNER + c] = (v0 + v1 + v2) * (1.0f / 3.0f);
    }
}

// ---------------------------------------------------------------------------
// In-place LayerNorm over last dim (1024) of d_out
// ---------------------------------------------------------------------------
__global__ void ln_kernel(float* __restrict__ y,
                          const float* __restrict__ g, const float* __restrict__ b)
{
    const int r = blockIdx.x;
    const size_t base = (size_t)r * DIM;
    float v[4];
    float s = 0.0f;
#pragma unroll
    for (int i = 0; i < 4; i++) {
        v[i] = y[base + threadIdx.x + i * 256];
        s += v[i];
    }
    __shared__ float red[8];
    __shared__ float mu_sh, rs_sh;
    for (int o = 16; o; o >>= 1) s += __shfl_xor_sync(0xffffffffu, s, o);
    if ((threadIdx.x & 31) == 0) red[threadIdx.x >> 5] = s;
    __syncthreads();
    if (threadIdx.x == 0) {
        float t = 0.0f;
        for (int i = 0; i < 8; i++) t += red[i];
        mu_sh = t / (float)DIM;
    }
    __syncthreads();
    const float mu = mu_sh;
    float q = 0.0f;
#pragma unroll
    for (int i = 0; i < 4; i++) { const float d = v[i] - mu; q += d * d; }
    __syncthreads();          // protect red[] reuse
    for (int o = 16; o; o >>= 1) q += __shfl_xor_sync(0xffffffffu, q, o);
    if ((threadIdx.x & 31) == 0) red[threadIdx.x >> 5] = q;
    __syncthreads();
    if (threadIdx.x == 0) {
        float t = 0.0f;
        for (int i = 0; i < 8; i++) t += red[i];
        rs_sh = rsqrtf(t / (float)DIM + 1e-5f);
    }
    __syncthreads();
    const float rs = rs_sh;
#pragma unroll
    for (int i = 0; i < 4; i++) {
        const int c = threadIdx.x + i * 256;
        y[base + c] = (v[i] - mu) * rs * g[c] + b[c];
    }
}

// ---------------------------------------------------------------------------
// Launcher
// ---------------------------------------------------------------------------
extern "C" void kernel_launch(void* const* d_in, const int* in_sizes, int n_in,
                              void* d_out, int out_size)
{
    const float* x         = (const float*)d_in[0];
    const float* in_proj_w = (const float*)d_in[1];
    const float* conv_w    = (const float*)d_in[2];
    const float* conv_b    = (const float*)d_in[3];
    const float* xproj_w   = (const float*)d_in[4];
    const float* dtproj_w  = (const float*)d_in[5];
    const float* dtproj_b  = (const float*)d_in[6];
    const float* D_param   = (const float*)d_in[7];
    const float* sw        = (const float*)d_in[8];
    const float* cg_w1     = (const float*)d_in[9];
    const float* cg_w2     = (const float*)d_in[10];
    const float* out_proj  = (const float*)d_in[11];
    const float* ln_g      = (const float*)d_in[12];
    const float* ln_b      = (const float*)d_in[13];
    float* out = (float*)d_out;

    float *xz, *xs1, *xs2, *y0, *y1, *y2, *b0, *b1, *b2, *fused, *ctx, *h;
    cudaGetSymbolAddress((void**)&xz,    g_xz);
    cudaGetSymbolAddress((void**)&xs1,   g_xs1);
    cudaGetSymbolAddress((void**)&xs2,   g_xs2);
    cudaGetSymbolAddress((void**)&y0,    g_y0);
    cudaGetSymbolAddress((void**)&y1,    g_y1);
    cudaGetSymbolAddress((void**)&y2,    g_y2);
    cudaGetSymbolAddress((void**)&b0,    g_B0);
    cudaGetSymbolAddress((void**)&b1,    g_B1);
    cudaGetSymbolAddress((void**)&b2,    g_B2);
    cudaGetSymbolAddress((void**)&fused, g_fused);
    cudaGetSymbolAddress((void**)&ctx,   g_ctx);
    cudaGetSymbolAddress((void**)&h,     g_h);

    // 1) xz = x @ in_proj_w  (16384 x 4096, K=1024)
    sgemm_kernel<0><<<dim3(2 * DINNER / BN, MTOK / BM), 256>>>(
        x, in_proj_w, xz, MTOK, 2 * DINNER, DIM, nullptr);

    // 2) downsample x_in (first half of xz)
    down_kernel<<<MTOK / 2, 256>>>(xz, xs1, 2, TLEN / 2);
    down_kernel<<<MTOK / 4, 256>>>(xz, xs2, 4, TLEN / 4);

    // 3) per-scale SSM core
    // scale 0 (X = x_in view in xz, stride 4096)
    conv_silu_kernel<<<MTOK, 256>>>(xz, 2 * DINNER,
                                    conv_w + 0 * DINNER * KCONV,
                                    conv_b + 0 * DINNER, y0, TLEN);
    bssm_kernel<<<MTOK, 256>>>(y0, xproj_w + 0 * DINNER * 2 * DSTATE, b0);
    dty_kernel<<<MTOK, 256>>>(y0, b0,
                              dtproj_w + 0 * DSTATE * DINNER,
                              dtproj_b + 0 * DINNER,
                              D_param + 0 * DINNER, xz, 2 * DINNER);
    // scale 1
    conv_silu_kernel<<<MTOK / 2, 256>>>(xs1, DINNER,
                                        conv_w + 1 * DINNER * KCONV,
                                        conv_b + 1 * DINNER, y1, TLEN / 2);
    bssm_kernel<<<MTOK / 2, 256>>>(y1, xproj_w + 1 * DINNER * 2 * DSTATE, b1);
    dty_kernel<<<MTOK / 2, 256>>>(y1, b1,
                                  dtproj_w + 1 * DSTATE * DINNER,
                                  dtproj_b + 1 * DINNER,
                                  D_param + 1 * DINNER, xs1, DINNER);
    // scale 2
    conv_silu_kernel<<<MTOK / 4, 256>>>(xs2, DINNER,
                                        conv_w + 2 * DINNER * KCONV,
                                        conv_b + 2 * DINNER, y2, TLEN / 4);
    bssm_kernel<<<MTOK / 4, 256>>>(y2, xproj_w + 2 * DINNER * 2 * DSTATE, b2);
    dty_kernel<<<MTOK / 4, 256>>>(y2, b2,
                                  dtproj_w + 2 * DSTATE * DINNER,
                                  dtproj_b + 2 * DINNER,
                                  D_param + 2 * DINNER, xs2, DINNER);

    // 4) upsample + softmax-weighted fuse + ctx
    mix_kernel<<<MTOK, 256>>>(y0, y1, y2, sw, fused, ctx);

    // 5) h = silu(ctx @ cg_w1)   (16384 x 1024, K=2048)
    sgemm_kernel<1><<<dim3((DINNER / 2) / BN, MTOK / BM), 256>>>(
        ctx, cg_w1, h, MTOK, DINNER / 2, DINNER, nullptr);

    // 6) fused *= sigmoid(h @ cg_w2) * silu(gate)   (16384 x 2048, K=1024)
    sgemm_kernel<2><<<dim3(DINNER / BN, MTOK / BM), 256>>>(
        h, cg_w2, fused, MTOK, DINNER, DINNER / 2, xz);

    // 7) out = fused @ out_proj + residual   (16384 x 1024, K=2048)
    sgemm_kernel<3><<<dim3(DIM / BN, MTOK / BM), 256>>>(
        fused, out_proj, out, MTOK, DIM, DINNER, x);

    // 8) in-place LayerNorm on out
    ln_kernel<<<MTOK, 256>>>(out, ln_g, ln_b);
}

// round 6
// speedup vs baseline: 2.7055x; 2.7055x over previous
#include <cuda_runtime.h>
#include <math.h>
#include <stdint.h>

// ---------------------------------------------------------------------------
// Problem constants
// ---------------------------------------------------------------------------
#define BATCH     4
#define TLEN      4096
#define MTOK      (BATCH * TLEN)      // 16384 tokens
#define DIM       1024
#define DINNER    2048
#define DSTATE    16
#define KCONV     4

// ---------------------------------------------------------------------------
// Scratch buffers (static device globals; no allocation anywhere)
// ---------------------------------------------------------------------------
__device__ float g_xz   [(size_t)MTOK * 2 * DINNER];
__device__ float g_xs1  [(size_t)(MTOK/2) * DINNER];
__device__ float g_xs2  [(size_t)(MTOK/4) * DINNER];
__device__ float g_y0   [(size_t)MTOK     * DINNER];
__device__ float g_y1   [(size_t)(MTOK/2) * DINNER];
__device__ float g_y2   [(size_t)(MTOK/4) * DINNER];
__device__ float g_B0   [(size_t)MTOK     * DSTATE];
__device__ float g_B1   [(size_t)(MTOK/2) * DSTATE];
__device__ float g_B2   [(size_t)(MTOK/4) * DSTATE];
__device__ float g_fused[(size_t)MTOK * DINNER];
__device__ float g_ctx  [(size_t)MTOK * DINNER];
__device__ float g_h    [(size_t)MTOK * (DINNER/2)];
// transposed weights ([N,K], pre-rounded to tf32)
__device__ float g_wT   [(size_t)(DIM*2*DINNER) + (size_t)(DINNER*(DINNER/2))
                         + (size_t)((DINNER/2)*DINNER) + (size_t)(DINNER*DIM)];

// ---------------------------------------------------------------------------
// Math helpers
// ---------------------------------------------------------------------------
__device__ __forceinline__ float sigmoidf_(float x) { return 1.0f / (1.0f + expf(-x)); }
__device__ __forceinline__ float siluf_(float x)    { return x / (1.0f + expf(-x)); }
__device__ __forceinline__ float softplusf_(float x) {
    return x > 0.0f ? x + log1pf(expf(-x)) : log1pf(expf(x));
}
__device__ __forceinline__ float to_tf32(float x) {
    uint32_t r;
    asm("cvt.rna.tf32.f32 %0, %1;" : "=r"(r) : "f"(x));
    return __uint_as_float(r);
}

// ---------------------------------------------------------------------------
// PTX helpers (base-ISA: cp.async / ldmatrix / mma.sync tf32)
// ---------------------------------------------------------------------------
__device__ __forceinline__ uint32_t smem_u32(const void* p) {
    uint32_t a;
    asm("{ .reg .u64 t; cvta.to.shared.u64 t, %1; cvt.u32.u64 %0, t; }" : "=r"(a) : "l"(p));
    return a;
}
__device__ __forceinline__ void cp_async16(uint32_t saddr, const void* gaddr) {
    asm volatile("cp.async.cg.shared.global [%0], [%1], 16;"
                 :: "r"(saddr), "l"(gaddr) : "memory");
}
#define CP_COMMIT() asm volatile("cp.async.commit_group;" ::: "memory")
#define CP_WAIT(n)  asm volatile("cp.async.wait_group %0;" :: "n"(n) : "memory")

__device__ __forceinline__ void ldsm_x4(uint32_t* r, uint32_t addr) {
    asm volatile("ldmatrix.sync.aligned.m8n8.x4.shared.b16 {%0,%1,%2,%3}, [%4];"
                 : "=r"(r[0]), "=r"(r[1]), "=r"(r[2]), "=r"(r[3]) : "r"(addr));
}
__device__ __forceinline__ void mma_tf32(float* d, const uint32_t* a, const uint32_t* b) {
    asm volatile(
        "mma.sync.aligned.m16n8k8.row.col.f32.tf32.tf32.f32 "
        "{%0,%1,%2,%3}, {%4,%5,%6,%7}, {%8,%9}, {%0,%1,%2,%3};"
        : "+f"(d[0]), "+f"(d[1]), "+f"(d[2]), "+f"(d[3])
        : "r"(a[0]), "r"(a[1]), "r"(a[2]), "r"(a[3]), "r"(b[0]), "r"(b[1]));
}

// ---------------------------------------------------------------------------
// TF32 tensor-core GEMM: C[M,N] = A[M,K] @ Bt[N,K]^T
// A row-major fp32 (converted to tf32 at fragment load), Bt pre-rounded tf32.
// Tiles 128x128x32, 8 warps (2x4), warp tile 64x32, 3-stage cp.async pipeline.
// Smem rows: 128B (32 floats), 16B units swizzled u ^= (row & 7).
// EPI: 0 plain, 1 silu, 2 cg-combine (C in/out = fused, aux = xz gate),
//      3 +residual (aux)
// ---------------------------------------------------------------------------
#define STAGES     3
#define TILE_BYTES 16384                  // 128 rows * 128B
#define SM_TOTAL   (STAGES * 2 * TILE_BYTES)   // 98304

template <int EPI>
__global__ __launch_bounds__(256, 2)
void tgemm_kernel(const float* __restrict__ A, const float* __restrict__ Bt,
                  float* __restrict__ C, int M, int N, int K,
                  const float* __restrict__ aux)
{
    extern __shared__ char smem[];
    const uint32_t sbase = smem_u32(smem);
    const int tid = threadIdx.x;
    const int lid = tid & 31;
    const int wid = tid >> 5;
    const int warp_m = wid & 1;       // 2 x 64 rows
    const int warp_n = wid >> 1;      // 4 x 32 cols
    const int bn = blockIdx.x, bm = blockIdx.y;
    const int g = lid >> 2, tig = lid & 3;

    const float* Abase = A  + (size_t)bm * 128 * K;
    const float* Bbase = Bt + (size_t)bn * 128 * K;
    const int nk = K >> 5;            // chunks of 32 floats

    // copy one 128x32f tile of A and B into stage buf
    auto issue_copy = [&](int chunk, int buf) {
        const int k0 = chunk << 5;
        const int u  = tid & 7;                 // 16B unit in row
        const uint32_t sa = sbase + buf * (2 * TILE_BYTES);
        const uint32_t sb = sa + TILE_BYTES;
#pragma unroll
        for (int i = 0; i < 4; i++) {
            const int r = (tid >> 3) + i * 32;
            const uint32_t so = (uint32_t)(r * 128 + ((u ^ (r & 7)) << 4));
            cp_async16(sa + so, Abase + (size_t)r * K + k0 + u * 4);
            cp_async16(sb + so, Bbase + (size_t)r * K + k0 + u * 4);
        }
        CP_COMMIT();
    };

    float acc[4][4][4];
#pragma unroll
    for (int i = 0; i < 4; i++)
#pragma unroll
        for (int j = 0; j < 4; j++)
#pragma unroll
            for (int c = 0; c < 4; c++) acc[i][j][c] = 0.0f;

    issue_copy(0, 0);
    if (nk > 1) issue_copy(1, 1);

    const int mi  = lid >> 3;         // ldmatrix sub-matrix index 0..3
    const int lr  = lid & 7;          // row within 8-row sub-matrix

    for (int it = 0; it < nk; ++it) {
        if (it + 2 < nk) { issue_copy(it + 2, (it + 2) % STAGES); CP_WAIT(2); }
        else if (it + 1 < nk) { CP_WAIT(1); }
        else { CP_WAIT(0); }
        __syncthreads();

        const uint32_t a_s = sbase + (it % STAGES) * (2 * TILE_BYTES);
        const uint32_t b_s = a_s + TILE_BYTES;

#pragma unroll
        for (int ks = 0; ks < 4; ks++) {
            const int ub = ks * 2;   // 16B-unit base of this k-step (8 floats)

            uint32_t af[4][4];
#pragma unroll
            for (int mf = 0; mf < 4; mf++) {
                const int row  = warp_m * 64 + mf * 16 + (mi & 1) * 8 + lr;
                const int unit = ub + (mi >> 1);
                ldsm_x4(af[mf], a_s + (uint32_t)(row * 128 + ((unit ^ (row & 7)) << 4)));
            }
            uint32_t bf[4][2];
#pragma unroll
            for (int p = 0; p < 2; p++) {
                const int row  = warp_n * 32 + p * 16 + (mi >> 1) * 8 + lr;
                const int unit = ub + (mi & 1);
                uint32_t t[4];
                ldsm_x4(t, b_s + (uint32_t)(row * 128 + ((unit ^ (row & 7)) << 4)));
                bf[p * 2][0] = t[0]; bf[p * 2][1] = t[1];
                bf[p * 2 + 1][0] = t[2]; bf[p * 2 + 1][1] = t[3];
            }
            // A fragments: round fp32 -> tf32 (B was pre-rounded at transpose)
#pragma unroll
            for (int mf = 0; mf < 4; mf++)
#pragma unroll
                for (int q = 0; q < 4; q++)
                    af[mf][q] = __float_as_uint(to_tf32(__uint_as_float(af[mf][q])));

#pragma unroll
            for (int mf = 0; mf < 4; mf++)
#pragma unroll
                for (int nf = 0; nf < 4; nf++)
                    mma_tf32(acc[mf][nf], af[mf], bf[nf]);
        }
        __syncthreads();
    }

    // Epilogue (registers -> gmem, fused elementwise)
#pragma unroll
    for (int mf = 0; mf < 4; mf++)
#pragma unroll
        for (int nf = 0; nf < 4; nf++)
#pragma unroll
            for (int hh = 0; hh < 2; hh++) {
                const int row = bm * 128 + warp_m * 64 + mf * 16 + g + hh * 8;
                const int col = bn * 128 + warp_n * 32 + nf * 8 + tig * 2;
                float2 v = make_float2(acc[mf][nf][hh * 2], acc[mf][nf][hh * 2 + 1]);
                const size_t idx = (size_t)row * N + col;
                if (EPI == 0) {
                    *(float2*)(C + idx) = v;
                } else if (EPI == 1) {
                    v.x = siluf_(v.x); v.y = siluf_(v.y);
                    *(float2*)(C + idx) = v;
                } else if (EPI == 2) {
                    const float2 f  = *(const float2*)(C + idx);
                    const float2 gt = *(const float2*)(aux + (size_t)row * (2 * DINNER)
                                                       + DINNER + col);
                    v.x = f.x * sigmoidf_(v.x) * siluf_(gt.x);
                    v.y = f.y * sigmoidf_(v.y) * siluf_(gt.y);
                    *(float2*)(C + idx) = v;
                } else {
                    const float2 rr = *(const float2*)(aux + idx);
                    v.x += rr.x; v.y += rr.y;
                    *(float2*)(C + idx) = v;
                }
            }
}

// ---------------------------------------------------------------------------
// Weight transpose: in[K,N] -> out[N,K], rounding to tf32 on the way
// ---------------------------------------------------------------------------
__global__ void transpose_kernel(const float* __restrict__ in, float* __restrict__ out,
                                 int K, int N)
{
    __shared__ float t[32][33];
    const int n0 = blockIdx.x * 32, k0 = blockIdx.y * 32;
    const int tx = threadIdx.x, ty = threadIdx.y;
#pragma unroll
    for (int i = 0; i < 32; i += 8)
        t[ty + i][tx] = in[(size_t)(k0 + ty + i) * N + n0 + tx];
    __syncthreads();
#pragma unroll
    for (int i = 0; i < 32; i += 8)
        out[(size_t)(n0 + ty + i) * K + k0 + tx] = to_tf32(t[tx][ty + i]);
}

// ---------------------------------------------------------------------------
// Downsample (mean pooling over time, factor 2 or 4) from x_in half of g_xz
// ---------------------------------------------------------------------------
__global__ void down_kernel(const float* __restrict__ xz, float* __restrict__ out,
                            int factor, int Tout)
{
    const int r = blockIdx.x;
    const int b = r / Tout, t = r % Tout;
    const float inv = 1.0f / (float)factor;
    const size_t srow = ((size_t)b * TLEN + (size_t)t * factor) * (2 * DINNER);
    for (int c4 = threadIdx.x; c4 < DINNER / 4; c4 += 256) {
        const int c = c4 * 4;
        float4 s = make_float4(0.f, 0.f, 0.f, 0.f);
        for (int k = 0; k < factor; k++) {
            const float4 v = *(const float4*)(xz + srow + (size_t)k * (2 * DINNER) + c);
            s.x += v.x; s.y += v.y; s.z += v.z; s.w += v.w;
        }
        s.x *= inv; s.y *= inv; s.z *= inv; s.w *= inv;
        *(float4*)(out + (size_t)r * DINNER + c) = s;
    }
}

// ---------------------------------------------------------------------------
// Causal depthwise conv (K=4) + SiLU, float4 over channels
// ---------------------------------------------------------------------------
__global__ void conv_silu_kernel(const float* __restrict__ X, int xstride,
                                 const float* __restrict__ w,
                                 const float* __restrict__ bias,
                                 float* __restrict__ out, int Ts)
{
    const int r = blockIdx.x;
    const int b = r / Ts, t = r % Ts;
    for (int c4 = threadIdx.x; c4 < DINNER / 4; c4 += 256) {
        const int c = c4 * 4;
        float4 acc = *(const float4*)(bias + c);
#pragma unroll
        for (int k = 0; k < KCONV; k++) {
            const int tt = t - (KCONV - 1) + k;
            if (tt >= 0) {
                const float4 xv = *(const float4*)(X + (size_t)(b * Ts + tt) * xstride + c);
                acc.x += w[(c + 0) * KCONV + k] * xv.x;
                acc.y += w[(c + 1) * KCONV + k] * xv.y;
                acc.z += w[(c + 2) * KCONV + k] * xv.z;
                acc.w += w[(c + 3) * KCONV + k] * xv.w;
            }
        }
        float4 o;
        o.x = siluf_(acc.x); o.y = siluf_(acc.y);
        o.z = siluf_(acc.z); o.w = siluf_(acc.w);
        *(float4*)(out + (size_t)r * DINNER + c) = o;
    }
}

// ---------------------------------------------------------------------------
// B_ssm = (xc @ xproj_w[:, :16])
// ---------------------------------------------------------------------------
__global__ void bssm_kernel(const float* __restrict__ xc,
                            const float* __restrict__ xw,   // (2048, 32)
                            float* __restrict__ Bout)
{
    const int row = blockIdx.x;
    const int tid = threadIdx.x;
    const int col = tid & 15;
    const int grp = tid >> 4;
    const float* xr = xc + (size_t)row * DINNER;
    float acc = 0.0f;
    const int k0 = grp * 128;
#pragma unroll 8
    for (int k = k0; k < k0 + 128; k++)
        acc += xr[k] * xw[k * (2 * DSTATE) + col];
    __shared__ float sh[16][16];
    sh[grp][col] = acc;
    __syncthreads();
    if (tid < 16) {
        float s = 0.0f;
#pragma unroll
        for (int gg = 0; gg < 16; gg++) s += sh[gg][tid];
        Bout[(size_t)row * DSTATE + tid] = s;
    }
}

// ---------------------------------------------------------------------------
// dt = softplus(B_ssm @ dtw + dtb);  y = xc * sigmoid(dt) + D * x_s (in-place)
// ---------------------------------------------------------------------------
__global__ void dty_kernel(float* __restrict__ y,
                           const float* __restrict__ Bssm,
                           const float* __restrict__ dtw,      // (16, 2048)
                           const float* __restrict__ dtb,
                           const float* __restrict__ Dp,
                           const float* __restrict__ xs, int xs_stride)
{
    const int row = blockIdx.x;
    __shared__ float Bv[DSTATE];
    if (threadIdx.x < DSTATE)
        Bv[threadIdx.x] = Bssm[(size_t)row * DSTATE + threadIdx.x];
    __syncthreads();
    for (int c = threadIdx.x; c < DINNER; c += 256) {
        float logit = dtb[c];
#pragma unroll
        for (int j = 0; j < DSTATE; j++)
            logit += Bv[j] * dtw[j * DINNER + c];
        const float dt = softplusf_(logit);
        const float xcv = y[(size_t)row * DINNER + c];
        y[(size_t)row * DINNER + c] =
            xcv * sigmoidf_(dt) + Dp[c] * xs[(size_t)row * xs_stride + c];
    }
}

// ---------------------------------------------------------------------------
// Linear upsample + softmax-weighted mix + ctx average
// ---------------------------------------------------------------------------
__global__ void mix_kernel(const float* __restrict__ y0,
                           const float* __restrict__ y1,
                           const float* __restrict__ y2,
                           const float* __restrict__ sw,
                           float* __restrict__ fused, float* __restrict__ ctx)
{
    const int r = blockIdx.x;
    const int b = r >> 12, t = r & (TLEN - 1);

    const float s0 = sw[0], s1 = sw[1], s2 = sw[2];
    const float m  = fmaxf(s0, fmaxf(s1, s2));
    const float e0 = expf(s0 - m), e1 = expf(s1 - m), e2 = expf(s2 - m);
    const float inv = 1.0f / (e0 + e1 + e2);
    const float w0 = e0 * inv, w1 = e1 * inv, w2 = e2 * inv;

    float c1 = fminf(fmaxf((t + 0.5f) * 0.5f - 0.5f, 0.0f), (float)(TLEN / 2 - 1));
    int lo1 = (int)floorf(c1);
    int hi1 = min(lo1 + 1, TLEN / 2 - 1);
    float f1 = c1 - (float)lo1;

    float c2 = fminf(fmaxf((t + 0.5f) * 0.25f - 0.5f, 0.0f), (float)(TLEN / 4 - 1));
    int lo2 = (int)floorf(c2);
    int hi2 = min(lo2 + 1, TLEN / 4 - 1);
    float f2 = c2 - (float)lo2;

    const float* p0  = y0 + (size_t)r * DINNER;
    const float* p1a = y1 + ((size_t)(b * (TLEN / 2) + lo1)) * DINNER;
    const float* p1b = y1 + ((size_t)(b * (TLEN / 2) + hi1)) * DINNER;
    const float* p2a = y2 + ((size_t)(b * (TLEN / 4) + lo2)) * DINNER;
    const float* p2b = y2 + ((size_t)(b * (TLEN / 4) + hi2)) * DINNER;

    for (int c = threadIdx.x; c < DINNER; c += 256) {
        const float v0 = p0[c];
        const float v1 = p1a[c] * (1.0f - f1) + p1b[c] * f1;
        const float v2 = p2a[c] * (1.0f - f2) + p2b[c] * f2;
        fused[(size_t)r * DINNER + c] = w0 * v0 + w1 * v1 + w2 * v2;
        ctx  [(size_t)r * DINNER + c] = (v0 + v1 + v2) * (1.0f / 3.0f);
    }
}

// ---------------------------------------------------------------------------
// In-place LayerNorm over last dim (1024)
// ---------------------------------------------------------------------------
__global__ void ln_kernel(float* __restrict__ y,
                          const float* __restrict__ g, const float* __restrict__ b)
{
    const int r = blockIdx.x;
    const size_t base = (size_t)r * DIM;
    float v[4];
    float s = 0.0f;
#pragma unroll
    for (int i = 0; i < 4; i++) {
        v[i] = y[base + threadIdx.x + i * 256];
        s += v[i];
    }
    __shared__ float red[8];
    __shared__ float mu_sh, rs_sh;
    for (int o = 16; o; o >>= 1) s += __shfl_xor_sync(0xffffffffu, s, o);
    if ((threadIdx.x & 31) == 0) red[threadIdx.x >> 5] = s;
    __syncthreads();
    if (threadIdx.x == 0) {
        float t = 0.0f;
        for (int i = 0; i < 8; i++) t += red[i];
        mu_sh = t / (float)DIM;
    }
    __syncthreads();
    const float mu = mu_sh;
    float q = 0.0f;
#pragma unroll
    for (int i = 0; i < 4; i++) { const float d = v[i] - mu; q += d * d; }
    __syncthreads();
    for (int o = 16; o; o >>= 1) q += __shfl_xor_sync(0xffffffffu, q, o);
    if ((threadIdx.x & 31) == 0) red[threadIdx.x >> 5] = q;
    __syncthreads();
    if (threadIdx.x == 0) {
        float t = 0.0f;
        for (int i = 0; i < 8; i++) t += red[i];
        rs_sh = rsqrtf(t / (float)DIM + 1e-5f);
    }
    __syncthreads();
    const float rs = rs_sh;
#pragma unroll
    for (int i = 0; i < 4; i++) {
        const int c = threadIdx.x + i * 256;
        y[base + c] = (v[i] - mu) * rs * g[c] + b[c];
    }
}

// ---------------------------------------------------------------------------
// Launcher
// ---------------------------------------------------------------------------
extern "C" void kernel_launch(void* const* d_in, const int* in_sizes, int n_in,
                              void* d_out, int out_size)
{
    const float* x         = (const float*)d_in[0];
    const float* in_proj_w = (const float*)d_in[1];
    const float* conv_w    = (const float*)d_in[2];
    const float* conv_b    = (const float*)d_in[3];
    const float* xproj_w   = (const float*)d_in[4];
    const float* dtproj_w  = (const float*)d_in[5];
    const float* dtproj_b  = (const float*)d_in[6];
    const float* D_param   = (const float*)d_in[7];
    const float* sw        = (const float*)d_in[8];
    const float* cg_w1     = (const float*)d_in[9];
    const float* cg_w2     = (const float*)d_in[10];
    const float* out_proj  = (const float*)d_in[11];
    const float* ln_g      = (const float*)d_in[12];
    const float* ln_b      = (const float*)d_in[13];
    float* out = (float*)d_out;

    float *xz, *xs1, *xs2, *y0, *y1, *y2, *b0, *b1, *b2, *fused, *ctx, *h, *wT;
    cudaGetSymbolAddress((void**)&xz,    g_xz);
    cudaGetSymbolAddress((void**)&xs1,   g_xs1);
    cudaGetSymbolAddress((void**)&xs2,   g_xs2);
    cudaGetSymbolAddress((void**)&y0,    g_y0);
    cudaGetSymbolAddress((void**)&y1,    g_y1);
    cudaGetSymbolAddress((void**)&y2,    g_y2);
    cudaGetSymbolAddress((void**)&b0,    g_B0);
    cudaGetSymbolAddress((void**)&b1,    g_B1);
    cudaGetSymbolAddress((void**)&b2,    g_B2);
    cudaGetSymbolAddress((void**)&fused, g_fused);
    cudaGetSymbolAddress((void**)&ctx,   g_ctx);
    cudaGetSymbolAddress((void**)&h,     g_h);
    cudaGetSymbolAddress((void**)&wT,    g_wT);

    float* wt_in  = wT;                                   // [4096, 1024]
    float* wt_cg1 = wt_in  + (size_t)DIM * 2 * DINNER;    // [1024, 2048]
    float* wt_cg2 = wt_cg1 + (size_t)DINNER * (DINNER/2); // [2048, 1024]
    float* wt_out = wt_cg2 + (size_t)(DINNER/2) * DINNER; // [1024, 2048]

    cudaFuncSetAttribute(tgemm_kernel<0>, cudaFuncAttributeMaxDynamicSharedMemorySize, SM_TOTAL);
    cudaFuncSetAttribute(tgemm_kernel<1>, cudaFuncAttributeMaxDynamicSharedMemorySize, SM_TOTAL);
    cudaFuncSetAttribute(tgemm_kernel<2>, cudaFuncAttributeMaxDynamicSharedMemorySize, SM_TOTAL);
    cudaFuncSetAttribute(tgemm_kernel<3>, cudaFuncAttributeMaxDynamicSharedMemorySize, SM_TOTAL);

    // 0) transpose weights to [N,K] (tf32-rounded)
    transpose_kernel<<<dim3((2*DINNER)/32, DIM/32),    dim3(32, 8)>>>(in_proj_w, wt_in,  DIM,      2*DINNER);
    transpose_kernel<<<dim3((DINNER/2)/32, DINNER/32), dim3(32, 8)>>>(cg_w1,     wt_cg1, DINNER,   DINNER/2);
    transpose_kernel<<<dim3(DINNER/32, (DINNER/2)/32), dim3(32, 8)>>>(cg_w2,     wt_cg2, DINNER/2, DINNER);
    transpose_kernel<<<dim3(DIM/32, DINNER/32),        dim3(32, 8)>>>(out_proj,  wt_out, DINNER,   DIM);

    // 1) xz = x @ in_proj_w  (16384 x 4096, K=1024)
    tgemm_kernel<0><<<dim3((2*DINNER)/128, MTOK/128), 256, SM_TOTAL>>>(
        x, wt_in, xz, MTOK, 2*DINNER, DIM, nullptr);

    // 2) downsample x_in
    down_kernel<<<MTOK / 2, 256>>>(xz, xs1, 2, TLEN / 2);
    down_kernel<<<MTOK / 4, 256>>>(xz, xs2, 4, TLEN / 4);

    // 3) per-scale SSM core
    conv_silu_kernel<<<MTOK, 256>>>(xz, 2 * DINNER,
                                    conv_w + 0 * DINNER * KCONV,
                                    conv_b + 0 * DINNER, y0, TLEN);
    bssm_kernel<<<MTOK, 256>>>(y0, xproj_w + 0 * DINNER * 2 * DSTATE, b0);
    dty_kernel<<<MTOK, 256>>>(y0, b0,
                              dtproj_w + 0 * DSTATE * DINNER,
                              dtproj_b + 0 * DINNER,
                              D_param + 0 * DINNER, xz, 2 * DINNER);
    conv_silu_kernel<<<MTOK / 2, 256>>>(xs1, DINNER,
                                        conv_w + 1 * DINNER * KCONV,
                                        conv_b + 1 * DINNER, y1, TLEN / 2);
    bssm_kernel<<<MTOK / 2, 256>>>(y1, xproj_w + 1 * DINNER * 2 * DSTATE, b1);
    dty_kernel<<<MTOK / 2, 256>>>(y1, b1,
                                  dtproj_w + 1 * DSTATE * DINNER,
                                  dtproj_b + 1 * DINNER,
                                  D_param + 1 * DINNER, xs1, DINNER);
    conv_silu_kernel<<<MTOK / 4, 256>>>(xs2, DINNER,
                                        conv_w + 2 * DINNER * KCONV,
                                        conv_b + 2 * DINNER, y2, TLEN / 4);
    bssm_kernel<<<MTOK / 4, 256>>>(y2, xproj_w + 2 * DINNER * 2 * DSTATE, b2);
    dty_kernel<<<MTOK / 4, 256>>>(y2, b2,
                                  dtproj_w + 2 * DSTATE * DINNER,
                                  dtproj_b + 2 * DINNER,
                                  D_param + 2 * DINNER, xs2, DINNER);

    // 4) upsample + fuse + ctx
    mix_kernel<<<MTOK, 256>>>(y0, y1, y2, sw, fused, ctx);

    // 5) h = silu(ctx @ cg_w1)   (16384 x 1024, K=2048)
    tgemm_kernel<1><<<dim3((DINNER/2)/128, MTOK/128), 256, SM_TOTAL>>>(
        ctx, wt_cg1, h, MTOK, DINNER/2, DINNER, nullptr);

    // 6) fused *= sigmoid(h @ cg_w2) * silu(gate)   (16384 x 2048, K=1024)
    tgemm_kernel<2><<<dim3(DINNER/128, MTOK/128), 256, SM_TOTAL>>>(
        h, wt_cg2, fused, MTOK, DINNER, DINNER/2, xz);

    // 7) out = fused @ out_proj + residual   (16384 x 1024, K=2048)
    tgemm_kernel<3><<<dim3(DIM/128, MTOK/128), 256, SM_TOTAL>>>(
        fused, wt_out, out, MTOK, DIM, DINNER, x);

    // 8) in-place LayerNorm
    ln_kernel<<<MTOK, 256>>>(out, ln_g, ln_b);
}

// round 7
// speedup vs baseline: 3.2580x; 1.2042x over previous
#include <cuda_runtime.h>
#include <cuda_fp16.h>
#include <math.h>
#include <stdint.h>

// ---------------------------------------------------------------------------
// Problem constants
// ---------------------------------------------------------------------------
#define BATCH     4
#define TLEN      4096
#define MTOK      (BATCH * TLEN)      // 16384 tokens
#define DIM       1024
#define DINNER    2048
#define DSTATE    16
#define KCONV     4

// ---------------------------------------------------------------------------
// Scratch buffers (static device globals; no allocation anywhere)
// ---------------------------------------------------------------------------
__device__ float  g_xz   [(size_t)MTOK * 2 * DINNER];   // fp32: x_in | gate
__device__ float  g_xs1  [(size_t)(MTOK/2) * DINNER];
__device__ float  g_xs2  [(size_t)(MTOK/4) * DINNER];
__device__ float  g_y0   [(size_t)MTOK     * DINNER];
__device__ float  g_y1   [(size_t)(MTOK/2) * DINNER];
__device__ float  g_y2   [(size_t)(MTOK/4) * DINNER];
__device__ float  g_fused[(size_t)MTOK * DINNER];       // fp32 (EPI2 input)
__device__ __half g_x_h    [(size_t)MTOK * DIM];
__device__ __half g_ctx_h  [(size_t)MTOK * DINNER];
__device__ __half g_h_h    [(size_t)MTOK * (DINNER/2)];
__device__ __half g_fused_h[(size_t)MTOK * DINNER];
// transposed half weights ([N,K])
__device__ __half g_wTh  [(size_t)(DIM*2*DINNER) + (size_t)(DINNER*(DINNER/2))
                          + (size_t)((DINNER/2)*DINNER) + (size_t)(DINNER*DIM)];

// ---------------------------------------------------------------------------
// Math helpers
// ---------------------------------------------------------------------------
__device__ __forceinline__ float sigmoidf_(float x) { return 1.0f / (1.0f + expf(-x)); }
__device__ __forceinline__ float siluf_(float x)    { return x / (1.0f + expf(-x)); }
__device__ __forceinline__ float softplusf_(float x) {
    return x > 0.0f ? x + log1pf(expf(-x)) : log1pf(expf(x));
}

// ---------------------------------------------------------------------------
// PTX helpers (base-ISA: cp.async / ldmatrix / mma.sync f16)
// ---------------------------------------------------------------------------
__device__ __forceinline__ uint32_t smem_u32(const void* p) {
    uint32_t a;
    asm("{ .reg .u64 t; cvta.to.shared.u64 t, %1; cvt.u32.u64 %0, t; }" : "=r"(a) : "l"(p));
    return a;
}
__device__ __forceinline__ void cp_async16(uint32_t saddr, const void* gaddr) {
    asm volatile("cp.async.cg.shared.global [%0], [%1], 16;"
                 :: "r"(saddr), "l"(gaddr) : "memory");
}
#define CP_COMMIT() asm volatile("cp.async.commit_group;" ::: "memory")
#define CP_WAIT(n)  asm volatile("cp.async.wait_group %0;" :: "n"(n) : "memory")

__device__ __forceinline__ void ldsm_x4(uint32_t* r, uint32_t addr) {
    asm volatile("ldmatrix.sync.aligned.m8n8.x4.shared.b16 {%0,%1,%2,%3}, [%4];"
                 : "=r"(r[0]), "=r"(r[1]), "=r"(r[2]), "=r"(r[3]) : "r"(addr));
}
__device__ __forceinline__ void mma_f16(float* d, const uint32_t* a, const uint32_t* b) {
    asm volatile(
        "mma.sync.aligned.m16n8k16.row.col.f32.f16.f16.f32 "
        "{%0,%1,%2,%3}, {%4,%5,%6,%7}, {%8,%9}, {%0,%1,%2,%3};"
        : "+f"(d[0]), "+f"(d[1]), "+f"(d[2]), "+f"(d[3])
        : "r"(a[0]), "r"(a[1]), "r"(a[2]), "r"(a[3]), "r"(b[0]), "r"(b[1]));
}

// ---------------------------------------------------------------------------
// FP16 tensor-core GEMM: C[M,N] = A[M,K] @ Bt[N,K]^T, fp32 accumulate.
// A, Bt half row-major. Tiles 128x128x64(halves), 8 warps (2x4),
// warp tile 64x32, 3-stage cp.async pipeline.
// Smem rows: 128B (64 halves), 16B units swizzled u ^= (row & 7).
// EPI: 0 plain f32 store, 1 silu -> half out, 2 cg-combine -> half out
//      (reads aux2 = fused f32, aux = xz gate), 3 +residual(aux) -> f32
// ---------------------------------------------------------------------------
#define STAGES      3
#define TILE_BYTESH 16384                     // 128 rows * 128B
#define SM_TOTALH   (STAGES * 2 * TILE_BYTESH)   // 98304

template <int EPI>
__global__ __launch_bounds__(256, 2)
void tgemm_kernel(const __half* __restrict__ A, const __half* __restrict__ Bt,
                  void* __restrict__ Cv, int M, int N, int K,
                  const float* __restrict__ aux, const float* __restrict__ aux2)
{
    extern __shared__ char smem[];
    const uint32_t sbase = smem_u32(smem);
    const int tid = threadIdx.x;
    const int lid = tid & 31;
    const int wid = tid >> 5;
    const int warp_m = wid & 1;       // 2 x 64 rows
    const int warp_n = wid >> 1;      // 4 x 32 cols
    const int bn = blockIdx.x, bm = blockIdx.y;

    const __half* Abase = A  + (size_t)bm * 128 * K;
    const __half* Bbase = Bt + (size_t)bn * 128 * K;
    const int nk = K >> 6;            // chunks of 64 halves

    auto issue_copy = [&](int chunk, int buf) {
        const int k0 = chunk << 6;
        const int u  = tid & 7;                 // 16B unit in row
        const uint32_t sa = sbase + buf * (2 * TILE_BYTESH);
        const uint32_t sb = sa + TILE_BYTESH;
#pragma unroll
        for (int i = 0; i < 4; i++) {
            const int r = (tid >> 3) + i * 32;
            const uint32_t so = (uint32_t)(r * 128 + ((u ^ (r & 7)) << 4));
            cp_async16(sa + so, Abase + (size_t)r * K + k0 + u * 8);
            cp_async16(sb + so, Bbase + (size_t)r * K + k0 + u * 8);
        }
        CP_COMMIT();
    };

    float acc[4][4][4];
#pragma unroll
    for (int i = 0; i < 4; i++)
#pragma unroll
        for (int j = 0; j < 4; j++)
#pragma unroll
            for (int c = 0; c < 4; c++) acc[i][j][c] = 0.0f;

    issue_copy(0, 0);
    if (nk > 1) issue_copy(1, 1);

    for (int it = 0; it < nk; ++it) {
        if (it + 2 < nk) { issue_copy(it + 2, (it + 2) % STAGES); CP_WAIT(2); }
        else if (it + 1 < nk) { CP_WAIT(1); }
        else { CP_WAIT(0); }
        __syncthreads();

        const uint32_t a_s = sbase + (it % STAGES) * (2 * TILE_BYTESH);
        const uint32_t b_s = a_s + TILE_BYTESH;

#pragma unroll
        for (int ks = 0; ks < 4; ks++) {
            const int ub = ks * 2;   // 16B-unit base of this k16 step

            uint32_t af[4][4];
#pragma unroll
            for (int mf = 0; mf < 4; mf++) {
                const int row  = warp_m * 64 + mf * 16 + (lid & 15);
                const int unit = ub + (lid >> 4);
                ldsm_x4(af[mf], a_s + (uint32_t)(row * 128 + ((unit ^ (row & 7)) << 4)));
            }
            uint32_t bf[4][2];
#pragma unroll
            for (int p = 0; p < 2; p++) {
                const int row  = warp_n * 32 + p * 16 + ((lid >> 4) & 1) * 8 + (lid & 7);
                const int unit = ub + ((lid >> 3) & 1);
                uint32_t t[4];
                ldsm_x4(t, b_s + (uint32_t)(row * 128 + ((unit ^ (row & 7)) << 4)));
                bf[p * 2][0] = t[0]; bf[p * 2][1] = t[1];
                bf[p * 2 + 1][0] = t[2]; bf[p * 2 + 1][1] = t[3];
            }
#pragma unroll
            for (int mf = 0; mf < 4; mf++)
#pragma unroll
                for (int nf = 0; nf < 4; nf++)
                    mma_f16(acc[mf][nf], af[mf], bf[nf]);
        }
        __syncthreads();
    }

    // Epilogue (registers -> gmem, fused elementwise)
#pragma unroll
    for (int mf = 0; mf < 4; mf++)
#pragma unroll
        for (int nf = 0; nf < 4; nf++)
#pragma unroll
            for (int hh = 0; hh < 2; hh++) {
                const int row = bm * 128 + warp_m * 64 + mf * 16 + (lid >> 2) + hh * 8;
                const int col = bn * 128 + warp_n * 32 + nf * 8 + (lid & 3) * 2;
                float2 v = make_float2(acc[mf][nf][hh * 2], acc[mf][nf][hh * 2 + 1]);
                const size_t idx = (size_t)row * N + col;
                if (EPI == 0) {
                    *(float2*)((float*)Cv + idx) = v;
                } else if (EPI == 1) {
                    *(__half2*)((__half*)Cv + idx) =
                        __floats2half2_rn(siluf_(v.x), siluf_(v.y));
                } else if (EPI == 2) {
                    const float2 f  = *(const float2*)(aux2 + idx);
                    const float2 gt = *(const float2*)(aux + (size_t)row * (2 * DINNER)
                                                       + DINNER + col);
                    const float ox = f.x * sigmoidf_(v.x) * siluf_(gt.x);
                    const float oy = f.y * sigmoidf_(v.y) * siluf_(gt.y);
                    *(__half2*)((__half*)Cv + idx) = __floats2half2_rn(ox, oy);
                } else {
                    const float2 rr = *(const float2*)(aux + idx);
                    v.x += rr.x; v.y += rr.y;
                    *(float2*)((float*)Cv + idx) = v;
                }
            }
}

// ---------------------------------------------------------------------------
// fp32 -> fp16 convert (float4 -> half2 x2)
// ---------------------------------------------------------------------------
__global__ void f2h_kernel(const float* __restrict__ in, __half* __restrict__ out,
                           int n4)
{
    const int i = blockIdx.x * 256 + threadIdx.x;
    if (i < n4) {
        const float4 v = *(const float4*)(in + (size_t)i * 4);
        ((__half2*)out)[(size_t)i * 2]     = __floats2half2_rn(v.x, v.y);
        ((__half2*)out)[(size_t)i * 2 + 1] = __floats2half2_rn(v.z, v.w);
    }
}

// ---------------------------------------------------------------------------
// Weight transpose: in[K,N] fp32 -> out[N,K] fp16
// ---------------------------------------------------------------------------
__global__ void transpose_kernel(const float* __restrict__ in, __half* __restrict__ out,
                                 int K, int N)
{
    __shared__ float t[32][33];
    const int n0 = blockIdx.x * 32, k0 = blockIdx.y * 32;
    const int tx = threadIdx.x, ty = threadIdx.y;
#pragma unroll
    for (int i = 0; i < 32; i += 8)
        t[ty + i][tx] = in[(size_t)(k0 + ty + i) * N + n0 + tx];
    __syncthreads();
#pragma unroll
    for (int i = 0; i < 32; i += 8)
        out[(size_t)(n0 + ty + i) * K + k0 + tx] = __float2half(t[tx][ty + i]);
}

// ---------------------------------------------------------------------------
// Downsample (mean pooling over time) from x_in half of g_xz
// ---------------------------------------------------------------------------
__global__ void down_kernel(const float* __restrict__ xz, float* __restrict__ out,
                            int factor, int Tout)
{
    const int r = blockIdx.x;
    const int b = r / Tout, t = r % Tout;
    const float inv = 1.0f / (float)factor;
    const size_t srow = ((size_t)b * TLEN + (size_t)t * factor) * (2 * DINNER);
    for (int c4 = threadIdx.x; c4 < DINNER / 4; c4 += 256) {
        const int c = c4 * 4;
        float4 s = make_float4(0.f, 0.f, 0.f, 0.f);
        for (int k = 0; k < factor; k++) {
            const float4 v = *(const float4*)(xz + srow + (size_t)k * (2 * DINNER) + c);
            s.x += v.x; s.y += v.y; s.z += v.z; s.w += v.w;
        }
        s.x *= inv; s.y *= inv; s.z *= inv; s.w *= inv;
        *(float4*)(out + (size_t)r * DINNER + c) = s;
    }
}

// ---------------------------------------------------------------------------
// Fused SSM core (per row): causal dwconv(K=4)+silu -> B_ssm -> dt -> y
// One block of 256 threads per token row; each thread owns 8 channels.
// ---------------------------------------------------------------------------
__global__ __launch_bounds__(256)
void ssm_kernel(const float* __restrict__ X, int xstride,
                const float* __restrict__ cw,   // (2048,4)
                const float* __restrict__ cb,   // (2048)
                const float* __restrict__ xw,   // (2048,32) use cols 0..15
                const float* __restrict__ dtw,  // (16,2048)
                const float* __restrict__ dtb,  // (2048)
                const float* __restrict__ Dp,   // (2048)
                float* __restrict__ y, int Ts)
{
    __shared__ float s_wp[8][16];
    __shared__ float s_B[DSTATE];
    const int r = blockIdx.x;
    const int b = r / Ts, t = r % Ts;
    const int c0 = threadIdx.x * 8;
    const int lane = threadIdx.x & 31, warp = threadIdx.x >> 5;

    // conv weights (per-channel 4 taps, contiguous)
    float4 wv[8];
#pragma unroll
    for (int i = 0; i < 8; i++) wv[i] = *(const float4*)(cw + (size_t)(c0 + i) * 4);

    float acc[8];
    {
        const float4 b1 = *(const float4*)(cb + c0);
        const float4 b2 = *(const float4*)(cb + c0 + 4);
        acc[0]=b1.x; acc[1]=b1.y; acc[2]=b1.z; acc[3]=b1.w;
        acc[4]=b2.x; acc[5]=b2.y; acc[6]=b2.z; acc[7]=b2.w;
    }
    float xcur[8];
#pragma unroll
    for (int k = 0; k < KCONV; k++) {
        const int tt = t - (KCONV - 1) + k;
        if (tt < 0) continue;
        const float* Xr = X + (size_t)(b * Ts + tt) * xstride + c0;
        const float4 xa = *(const float4*)(Xr);
        const float4 xb = *(const float4*)(Xr + 4);
        float xv[8] = {xa.x, xa.y, xa.z, xa.w, xb.x, xb.y, xb.z, xb.w};
        if (k == KCONV - 1) {
#pragma unroll
            for (int i = 0; i < 8; i++) xcur[i] = xv[i];
        }
        const float wk[8] = {k==0?wv[0].x:k==1?wv[0].y:k==2?wv[0].z:wv[0].w,
                             k==0?wv[1].x:k==1?wv[1].y:k==2?wv[1].z:wv[1].w,
                             k==0?wv[2].x:k==1?wv[2].y:k==2?wv[2].z:wv[2].w,
                             k==0?wv[3].x:k==1?wv[3].y:k==2?wv[3].z:wv[3].w,
                             k==0?wv[4].x:k==1?wv[4].y:k==2?wv[4].z:wv[4].w,
                             k==0?wv[5].x:k==1?wv[5].y:k==2?wv[5].z:wv[5].w,
                             k==0?wv[6].x:k==1?wv[6].y:k==2?wv[6].z:wv[6].w,
                             k==0?wv[7].x:k==1?wv[7].y:k==2?wv[7].z:wv[7].w};
#pragma unroll
        for (int i = 0; i < 8; i++) acc[i] += wk[i] * xv[i];
    }
    float xc[8];
#pragma unroll
    for (int i = 0; i < 8; i++) xc[i] = siluf_(acc[i]);

    // B_ssm partials: part[j] = sum_c xc[c] * xw[c][j], j < 16
    float part[16];
#pragma unroll
    for (int j = 0; j < 16; j++) part[j] = 0.0f;
#pragma unroll
    for (int i = 0; i < 8; i++) {
        const float* xr = xw + (size_t)(c0 + i) * (2 * DSTATE);
        const float4 x1 = *(const float4*)(xr);
        const float4 x2 = *(const float4*)(xr + 4);
        const float4 x3 = *(const float4*)(xr + 8);
        const float4 x4 = *(const float4*)(xr + 12);
        const float xi = xc[i];
        part[0]  += xi * x1.x; part[1]  += xi * x1.y;
        part[2]  += xi * x1.z; part[3]  += xi * x1.w;
        part[4]  += xi * x2.x; part[5]  += xi * x2.y;
        part[6]  += xi * x2.z; part[7]  += xi * x2.w;
        part[8]  += xi * x3.x; part[9]  += xi * x3.y;
        part[10] += xi * x3.z; part[11] += xi * x3.w;
        part[12] += xi * x4.x; part[13] += xi * x4.y;
        part[14] += xi * x4.z; part[15] += xi * x4.w;
    }
#pragma unroll
    for (int j = 0; j < 16; j++)
#pragma unroll
        for (int o = 16; o; o >>= 1)
            part[j] += __shfl_xor_sync(0xffffffffu, part[j], o);
    if (lane == 0) {
#pragma unroll
        for (int j = 0; j < 16; j++) s_wp[warp][j] = part[j];
    }
    __syncthreads();
    if (threadIdx.x < 16) {
        float s = 0.0f;
#pragma unroll
        for (int w = 0; w < 8; w++) s += s_wp[w][threadIdx.x];
        s_B[threadIdx.x] = s;
    }
    __syncthreads();

    // dt = softplus(B @ dtw + dtb);  y = xc * sigmoid(dt) + D * x
    float lo[8];
    {
        const float4 b1 = *(const float4*)(dtb + c0);
        const float4 b2 = *(const float4*)(dtb + c0 + 4);
        lo[0]=b1.x; lo[1]=b1.y; lo[2]=b1.z; lo[3]=b1.w;
        lo[4]=b2.x; lo[5]=b2.y; lo[6]=b2.z; lo[7]=b2.w;
    }
#pragma unroll
    for (int j = 0; j < DSTATE; j++) {
        const float bj = s_B[j];
        const float4 d1 = *(const float4*)(dtw + (size_t)j * DINNER + c0);
        const float4 d2 = *(const float4*)(dtw + (size_t)j * DINNER + c0 + 4);
        lo[0] += bj * d1.x; lo[1] += bj * d1.y; lo[2] += bj * d1.z; lo[3] += bj * d1.w;
        lo[4] += bj * d2.x; lo[5] += bj * d2.y; lo[6] += bj * d2.z; lo[7] += bj * d2.w;
    }
    const float4 D1 = *(const float4*)(Dp + c0);
    const float4 D2 = *(const float4*)(Dp + c0 + 4);
    const float Dv[8] = {D1.x, D1.y, D1.z, D1.w, D2.x, D2.y, D2.z, D2.w};
    float yv[8];
#pragma unroll
    for (int i = 0; i < 8; i++)
        yv[i] = xc[i] * sigmoidf_(softplusf_(lo[i])) + Dv[i] * xcur[i];
    *(float4*)(y + (size_t)r * DINNER + c0)     = make_float4(yv[0], yv[1], yv[2], yv[3]);
    *(float4*)(y + (size_t)r * DINNER + c0 + 4) = make_float4(yv[4], yv[5], yv[6], yv[7]);
}

// ---------------------------------------------------------------------------
// Linear upsample + softmax-weighted mix (fused f32) + ctx average (half)
// ---------------------------------------------------------------------------
__global__ void mix_kernel(const float* __restrict__ y0,
                           const float* __restrict__ y1,
                           const float* __restrict__ y2,
                           const float* __restrict__ sw,
                           float* __restrict__ fused, __half* __restrict__ ctx_h)
{
    const int r = blockIdx.x;
    const int b = r >> 12, t = r & (TLEN - 1);

    const float s0 = sw[0], s1 = sw[1], s2 = sw[2];
    const float m  = fmaxf(s0, fmaxf(s1, s2));
    const float e0 = expf(s0 - m), e1 = expf(s1 - m), e2 = expf(s2 - m);
    const float inv = 1.0f / (e0 + e1 + e2);
    const float w0 = e0 * inv, w1 = e1 * inv, w2 = e2 * inv;

    float c1 = fminf(fmaxf((t + 0.5f) * 0.5f - 0.5f, 0.0f), (float)(TLEN / 2 - 1));
    int lo1 = (int)floorf(c1);
    int hi1 = min(lo1 + 1, TLEN / 2 - 1);
    float f1 = c1 - (float)lo1;

    float c2 = fminf(fmaxf((t + 0.5f) * 0.25f - 0.5f, 0.0f), (float)(TLEN / 4 - 1));
    int lo2 = (int)floorf(c2);
    int hi2 = min(lo2 + 1, TLEN / 4 - 1);
    float f2 = c2 - (float)lo2;

    const float* p0  = y0 + (size_t)r * DINNER;
    const float* p1a = y1 + ((size_t)(b * (TLEN / 2) + lo1)) * DINNER;
    const float* p1b = y1 + ((size_t)(b * (TLEN / 2) + hi1)) * DINNER;
    const float* p2a = y2 + ((size_t)(b * (TLEN / 4) + lo2)) * DINNER;
    const float* p2b = y2 + ((size_t)(b * (TLEN / 4) + hi2)) * DINNER;

    for (int c = threadIdx.x * 2; c < DINNER; c += 512) {
        const float2 v0  = *(const float2*)(p0 + c);
        const float2 a1  = *(const float2*)(p1a + c);
        const float2 b1v = *(const float2*)(p1b + c);
        const float2 a2  = *(const float2*)(p2a + c);
        const float2 b2v = *(const float2*)(p2b + c);
        const float u1x = a1.x * (1.0f - f1) + b1v.x * f1;
        const float u1y = a1.y * (1.0f - f1) + b1v.y * f1;
        const float u2x = a2.x * (1.0f - f2) + b2v.x * f2;
        const float u2y = a2.y * (1.0f - f2) + b2v.y * f2;
        const float fx = w0 * v0.x + w1 * u1x + w2 * u2x;
        const float fy = w0 * v0.y + w1 * u1y + w2 * u2y;
        *(float2*)(fused + (size_t)r * DINNER + c) = make_float2(fx, fy);
        *(__half2*)(ctx_h + (size_t)r * DINNER + c) =
            __floats2half2_rn((v0.x + u1x + u2x) * (1.0f / 3.0f),
                              (v0.y + u1y + u2y) * (1.0f / 3.0f));
    }
}

// ---------------------------------------------------------------------------
// In-place LayerNorm over last dim (1024)
// ---------------------------------------------------------------------------
__global__ void ln_kernel(float* __restrict__ y,
                          const float* __restrict__ g, const float* __restrict__ b)
{
    const int r = blockIdx.x;
    const size_t base = (size_t)r * DIM;
    float v[4];
    float s = 0.0f;
#pragma unroll
    for (int i = 0; i < 4; i++) {
        v[i] = y[base + threadIdx.x + i * 256];
        s += v[i];
    }
    __shared__ float red[8];
    __shared__ float mu_sh, rs_sh;
    for (int o = 16; o; o >>= 1) s += __shfl_xor_sync(0xffffffffu, s, o);
    if ((threadIdx.x & 31) == 0) red[threadIdx.x >> 5] = s;
    __syncthreads();
    if (threadIdx.x == 0) {
        float t = 0.0f;
        for (int i = 0; i < 8; i++) t += red[i];
        mu_sh = t / (float)DIM;
    }
    __syncthreads();
    const float mu = mu_sh;
    float q = 0.0f;
#pragma unroll
    for (int i = 0; i < 4; i++) { const float d = v[i] - mu; q += d * d; }
    __syncthreads();
    for (int o = 16; o; o >>= 1) q += __shfl_xor_sync(0xffffffffu, q, o);
    if ((threadIdx.x & 31) == 0) red[threadIdx.x >> 5] = q;
    __syncthreads();
    if (threadIdx.x == 0) {
        float t = 0.0f;
        for (int i = 0; i < 8; i++) t += red[i];
        rs_sh = rsqrtf(t / (float)DIM + 1e-5f);
    }
    __syncthreads();
    const float rs = rs_sh;
#pragma unroll
    for (int i = 0; i < 4; i++) {
        const int c = threadIdx.x + i * 256;
        y[base + c] = (v[i] - mu) * rs * g[c] + b[c];
    }
}

// ---------------------------------------------------------------------------
// Launcher
// ---------------------------------------------------------------------------
extern "C" void kernel_launch(void* const* d_in, const int* in_sizes, int n_in,
                              void* d_out, int out_size)
{
    const float* x         = (const float*)d_in[0];
    const float* in_proj_w = (const float*)d_in[1];
    const float* conv_w    = (const float*)d_in[2];
    const float* conv_b    = (const float*)d_in[3];
    const float* xproj_w   = (const float*)d_in[4];
    const float* dtproj_w  = (const float*)d_in[5];
    const float* dtproj_b  = (const float*)d_in[6];
    const float* D_param   = (const float*)d_in[7];
    const float* sw        = (const float*)d_in[8];
    const float* cg_w1     = (const float*)d_in[9];
    const float* cg_w2     = (const float*)d_in[10];
    const float* out_proj  = (const float*)d_in[11];
    const float* ln_g      = (const float*)d_in[12];
    const float* ln_b      = (const float*)d_in[13];
    float* out = (float*)d_out;

    float  *xz, *xs1, *xs2, *y0, *y1, *y2, *fused;
    __half *x_h, *ctx_h, *h_h, *fused_h, *wTh;
    cudaGetSymbolAddress((void**)&xz,      g_xz);
    cudaGetSymbolAddress((void**)&xs1,     g_xs1);
    cudaGetSymbolAddress((void**)&xs2,     g_xs2);
    cudaGetSymbolAddress((void**)&y0,      g_y0);
    cudaGetSymbolAddress((void**)&y1,      g_y1);
    cudaGetSymbolAddress((void**)&y2,      g_y2);
    cudaGetSymbolAddress((void**)&fused,   g_fused);
    cudaGetSymbolAddress((void**)&x_h,     g_x_h);
    cudaGetSymbolAddress((void**)&ctx_h,   g_ctx_h);
    cudaGetSymbolAddress((void**)&h_h,     g_h_h);
    cudaGetSymbolAddress((void**)&fused_h, g_fused_h);
    cudaGetSymbolAddress((void**)&wTh,     g_wTh);

    __half* wt_in  = wTh;                                  // [4096, 1024]
    __half* wt_cg1 = wt_in  + (size_t)DIM * 2 * DINNER;    // [1024, 2048]
    __half* wt_cg2 = wt_cg1 + (size_t)DINNER * (DINNER/2); // [2048, 1024]
    __half* wt_out = wt_cg2 + (size_t)(DINNER/2) * DINNER; // [1024, 2048]

    cudaFuncSetAttribute(tgemm_kernel<0>, cudaFuncAttributeMaxDynamicSharedMemorySize, SM_TOTALH);
    cudaFuncSetAttribute(tgemm_kernel<1>, cudaFuncAttributeMaxDynamicSharedMemorySize, SM_TOTALH);
    cudaFuncSetAttribute(tgemm_kernel<2>, cudaFuncAttributeMaxDynamicSharedMemorySize, SM_TOTALH);
    cudaFuncSetAttribute(tgemm_kernel<3>, cudaFuncAttributeMaxDynamicSharedMemorySize, SM_TOTALH);

    // 0) prepare half operands
    f2h_kernel<<<(MTOK * DIM / 4 + 255) / 256, 256>>>(x, x_h, MTOK * DIM / 4);
    transpose_kernel<<<dim3((2*DINNER)/32, DIM/32),    dim3(32, 8)>>>(in_proj_w, wt_in,  DIM,      2*DINNER);
    transpose_kernel<<<dim3((DINNER/2)/32, DINNER/32), dim3(32, 8)>>>(cg_w1,     wt_cg1, DINNER,   DINNER/2);
    transpose_kernel<<<dim3(DINNER/32, (DINNER/2)/32), dim3(32, 8)>>>(cg_w2,     wt_cg2, DINNER/2, DINNER);
    transpose_kernel<<<dim3(DIM/32, DINNER/32),        dim3(32, 8)>>>(out_proj,  wt_out, DINNER,   DIM);

    // 1) xz = x @ in_proj_w  (16384 x 4096, K=1024)
    tgemm_kernel<0><<<dim3((2*DINNER)/128, MTOK/128), 256, SM_TOTALH>>>(
        x_h, wt_in, xz, MTOK, 2*DINNER, DIM, nullptr, nullptr);

    // 2) downsample x_in
    down_kernel<<<MTOK / 2, 256>>>(xz, xs1, 2, TLEN / 2);
    down_kernel<<<MTOK / 4, 256>>>(xz, xs2, 4, TLEN / 4);

    // 3) per-scale fused SSM core
    ssm_kernel<<<MTOK, 256>>>(xz, 2 * DINNER,
                              conv_w + 0 * DINNER * KCONV, conv_b + 0 * DINNER,
                              xproj_w + 0 * DINNER * 2 * DSTATE,
                              dtproj_w + 0 * DSTATE * DINNER,
                              dtproj_b + 0 * DINNER, D_param + 0 * DINNER,
                              y0, TLEN);
    ssm_kernel<<<MTOK / 2, 256>>>(xs1, DINNER,
                              conv_w + 1 * DINNER * KCONV, conv_b + 1 * DINNER,
                              xproj_w + 1 * DINNER * 2 * DSTATE,
                              dtproj_w + 1 * DSTATE * DINNER,
                              dtproj_b + 1 * DINNER, D_param + 1 * DINNER,
                              y1, TLEN / 2);
    ssm_kernel<<<MTOK / 4, 256>>>(xs2, DINNER,
                              conv_w + 2 * DINNER * KCONV, conv_b + 2 * DINNER,
                              xproj_w + 2 * DINNER * 2 * DSTATE,
                              dtproj_w + 2 * DSTATE * DINNER,
                              dtproj_b + 2 * DINNER, D_param + 2 * DINNER,
                              y2, TLEN / 4);

    // 4) upsample + fuse (f32) + ctx (half)
    mix_kernel<<<MTOK, 256>>>(y0, y1, y2, sw, fused, ctx_h);

    // 5) h = silu(ctx @ cg_w1) -> half   (16384 x 1024, K=2048)
    tgemm_kernel<1><<<dim3((DINNER/2)/128, MTOK/128), 256, SM_TOTALH>>>(
        ctx_h, wt_cg1, h_h, MTOK, DINNER/2, DINNER, nullptr, nullptr);

    // 6) fused_h = fused * sigmoid(h @ cg_w2) * silu(gate)  (16384 x 2048, K=1024)
    tgemm_kernel<2><<<dim3(DINNER/128, MTOK/128), 256, SM_TOTALH>>>(
        h_h, wt_cg2, fused_h, MTOK, DINNER, DINNER/2, xz, fused);

    // 7) out = fused_h @ out_proj + residual   (16384 x 1024, K=2048)
    tgemm_kernel<3><<<dim3(DIM/128, MTOK/128), 256, SM_TOTALH>>>(
        fused_h, wt_out, out, MTOK, DIM, DINNER, x, nullptr);

    // 8) in-place LayerNorm
    ln_kernel<<<MTOK, 256>>>(out, ln_g, ln_b);
}